// round 3
// baseline (speedup 1.0000x reference)
#include <cuda_runtime.h>
#include <cuda_bf16.h>
#include <math_constants.h>

// Banded sparse attention:
//   B=256, S=128, D_MODEL=1024, H=16, Dh=64, band half-width W=4 (<=9 keys/query)
// One block per (b, h). 128 threads, thread t owns query t.
// K and V head-tiles staged in padded shared memory; Q row lives in registers.

namespace {
constexpr int S      = 128;   // sequence length
constexpr int DM     = 1024;  // d_model
constexpr int H      = 16;    // heads
constexpr int DH     = 64;    // head dim
constexpr int W      = 4;     // band half-width
constexpr int NB     = 2 * W + 1;  // 9 band positions
constexpr int LD     = 68;    // smem row stride (floats), 68%32=4 -> conflict-free for LDS.128
constexpr float SCALE = 0.125f;  // 64^-0.5

constexpr int THREADS = 128;
constexpr int SMEM_BYTES = 2 * S * LD * 4;  // K tile + V tile = 69632 B
}  // namespace

__global__ __launch_bounds__(THREADS)
void banded_attn_kernel(const float* __restrict__ q,
                        const float* __restrict__ k,
                        const float* __restrict__ v,
                        float* __restrict__ out) {
    const int h = blockIdx.x;
    const int b = blockIdx.y;
    const int tid = threadIdx.x;

    extern __shared__ float sm[];
    float* ks = sm;            // [S][LD]
    float* vs = sm + S * LD;   // [S][LD]

    // Base of this (b, h) tile in global memory (row s at +s*DM).
    const size_t gbase = (size_t)b * S * DM + (size_t)h * DH;

    // ---- Cooperative coalesced load of K and V tiles into smem ----
    // 2048 float4 elements per tile; 128 threads -> 16 iterations.
    // Consecutive lanes cover consecutive d4 -> 256B contiguous segments.
    #pragma unroll
    for (int it = 0; it < 16; ++it) {
        const int idx = it * THREADS + tid;
        const int s   = idx >> 4;        // row
        const int d4  = idx & 15;        // float4 column
        const size_t goff = gbase + (size_t)s * DM + d4 * 4;
        const float4 kv = *reinterpret_cast<const float4*>(k + goff);
        const float4 vv = *reinterpret_cast<const float4*>(v + goff);
        *reinterpret_cast<float4*>(ks + s * LD + d4 * 4) = kv;
        *reinterpret_cast<float4*>(vs + s * LD + d4 * 4) = vv;
    }

    // ---- Load this thread's Q row into registers ----
    const int i = tid;  // query index
    float4 qr[16];
    {
        const float4* qrow = reinterpret_cast<const float4*>(q + gbase + (size_t)i * DM);
        #pragma unroll
        for (int c = 0; c < 16; ++c) qr[c] = qrow[c];
    }

    __syncthreads();

    // ---- Scores over the 9 band positions (branch-free, clamped smem index) ----
    float sc[NB];
    #pragma unroll
    for (int jj = 0; jj < NB; ++jj) {
        const int j  = i - W + jj;
        const bool valid = (j >= 0) && (j < S);
        const int jc = min(max(j, 0), S - 1);
        const float4* kr = reinterpret_cast<const float4*>(ks + jc * LD);
        float acc = 0.0f;
        #pragma unroll
        for (int c = 0; c < 16; ++c) {
            const float4 kv = kr[c];
            acc = fmaf(qr[c].x, kv.x, acc);
            acc = fmaf(qr[c].y, kv.y, acc);
            acc = fmaf(qr[c].z, kv.z, acc);
            acc = fmaf(qr[c].w, kv.w, acc);
        }
        sc[jj] = valid ? acc * SCALE : -CUDART_INF_F;
    }

    // ---- Softmax over the band ----
    float m = sc[0];
    #pragma unroll
    for (int jj = 1; jj < NB; ++jj) m = fmaxf(m, sc[jj]);
    float sum = 0.0f;
    #pragma unroll
    for (int jj = 0; jj < NB; ++jj) {
        const float w = __expf(sc[jj] - m);  // exp(-inf - m) == 0 for masked slots
        sc[jj] = w;
        sum += w;
    }
    const float inv = 1.0f / sum;

    // ---- Output: weighted sum of 9 V rows, float4-vectorized ----
    float* orow = out + gbase + (size_t)i * DM;
    #pragma unroll
    for (int c = 0; c < 16; ++c) {
        float ax = 0.0f, ay = 0.0f, az = 0.0f, aw = 0.0f;
        #pragma unroll
        for (int jj = 0; jj < NB; ++jj) {
            const int j  = i - W + jj;
            const int jc = min(max(j, 0), S - 1);   // weight is 0 when clamped
            const float4 vv = *reinterpret_cast<const float4*>(vs + jc * LD + c * 4);
            const float wgt = sc[jj];
            ax = fmaf(wgt, vv.x, ax);
            ay = fmaf(wgt, vv.y, ay);
            az = fmaf(wgt, vv.z, az);
            aw = fmaf(wgt, vv.w, aw);
        }
        reinterpret_cast<float4*>(orow)[c] = make_float4(ax * inv, ay * inv, az * inv, aw * inv);
    }
}

extern "C" void kernel_launch(void* const* d_in, const int* in_sizes, int n_in,
                              void* d_out, int out_size) {
    const float* q = (const float*)d_in[0];
    const float* k = (const float*)d_in[1];
    const float* v = (const float*)d_in[2];
    float* out = (float*)d_out;

    const int B = in_sizes[0] / (S * DM);  // 256

    static bool attr_set = false;  // idempotent host-side attribute; not a stream op
    if (!attr_set) {
        cudaFuncSetAttribute(banded_attn_kernel,
                             cudaFuncAttributeMaxDynamicSharedMemorySize, SMEM_BYTES);
        attr_set = true;
    }

    dim3 grid(H, B);
    banded_attn_kernel<<<grid, THREADS, SMEM_BYTES>>>(q, k, v, out);
}

// round 5
// speedup vs baseline: 1.2718x; 1.2718x over previous
#include <cuda_runtime.h>
#include <cuda_bf16.h>
#include <math_constants.h>

// Banded sparse attention: B=256, S=128, DM=1024, H=16, Dh=64, band half-width 4.
// One block per (b,h), 128 threads.
// Work unit: query PAIR (2p, 2p+1) split across two lanes (l, l^16) of a warp,
// each lane owning half (32 dims) of the head. Band union of a pair = 10 rows,
// so each K/V smem chunk is read once and serves both queries.
// Smem layout: exact 64-float rows (256B, float4-aligned) with chunk rotation
// swizzle  phys_chunk = (c + (row>>1)) & 15  -> conflict-free LDS.128 phases.

namespace {
constexpr int S   = 128;
constexpr int DM  = 1024;
constexpr int H   = 16;
constexpr int DH  = 64;
constexpr int W   = 4;
constexpr int NR  = 2 * W + 2;   // 10 band-union rows per pair
constexpr float SCALE = 0.125f;

constexpr int THREADS = 128;
constexpr int ROWF = 64;                       // floats per smem row (exact)
constexpr int SMEM_BYTES = 2 * S * ROWF * 4;   // K + V = 65536 B -> 3 blocks/SM
}  // namespace

__device__ __forceinline__ int swz(int row, int chunk) {
    // physical float offset of 16B chunk `chunk` of row `row`
    return row * ROWF + (((chunk + (row >> 1)) & 15) << 2);
}

__global__ __launch_bounds__(THREADS)
void banded_attn_kernel(const float* __restrict__ q,
                        const float* __restrict__ k,
                        const float* __restrict__ v,
                        float* __restrict__ out) {
    const int h   = blockIdx.x;
    const int b   = blockIdx.y;
    const int tid = threadIdx.x;
    const int lane = tid & 31;
    const int warp = tid >> 5;

    extern __shared__ float sm[];
    float* ks = sm;              // [S][ROWF] swizzled
    float* vs = sm + S * ROWF;   // [S][ROWF] swizzled

    const size_t gbase = (size_t)b * S * DM + (size_t)h * DH;

    // Pair / half assignment: lanes l and l^16 share pair p, own halves 0/1.
    const int p    = warp * 16 + (lane & 15);
    const int half = lane >> 4;
    const int r0   = 2 * p;            // first query of the pair
    const int cbase = half * 8;        // this lane's first logical 16B chunk (of 16)

    // ---- This lane's half of both Q rows (8 float4 each) ----
    float4 q0[8], q1[8];
    {
        const float4* q0p = reinterpret_cast<const float4*>(q + gbase + (size_t)r0 * DM) + cbase;
        const float4* q1p = reinterpret_cast<const float4*>(q + gbase + (size_t)(r0 + 1) * DM) + cbase;
        #pragma unroll
        for (int c = 0; c < 8; ++c) { q0[c] = q0p[c]; q1[c] = q1p[c]; }
    }

    // ---- Cooperative coalesced K/V staging: 2048 float4/tile, 128 thr -> 16 iters ----
    #pragma unroll
    for (int it = 0; it < 16; ++it) {
        const int idx = it * THREADS + tid;
        const int s   = idx >> 4;      // row
        const int d4  = idx & 15;      // logical chunk
        const size_t goff = gbase + (size_t)s * DM + d4 * 4;
        const int soff = swz(s, d4);
        *reinterpret_cast<float4*>(ks + soff) = *reinterpret_cast<const float4*>(k + goff);
        *reinterpret_cast<float4*>(vs + soff) = *reinterpret_cast<const float4*>(v + goff);
    }
    __syncthreads();

    // ---- Clamped band-union rows (clamped rows end up with weight 0) ----
    int rc[NR];
    #pragma unroll
    for (int jj = 0; jj < NR; ++jj) rc[jj] = min(max(r0 - W + jj, 0), S - 1);

    // ---- Partial scores over this lane's 8 chunks, for both queries ----
    float d0[NR], d1[NR];
    #pragma unroll
    for (int jj = 0; jj < NR; ++jj) {
        const int r = rc[jj];
        float a0 = 0.0f, a1 = 0.0f;
        #pragma unroll
        for (int c = 0; c < 8; ++c) {
            const float4 kv = *reinterpret_cast<const float4*>(ks + swz(r, cbase + c));
            a0 = fmaf(q0[c].x, kv.x, a0); a0 = fmaf(q0[c].y, kv.y, a0);
            a0 = fmaf(q0[c].z, kv.z, a0); a0 = fmaf(q0[c].w, kv.w, a0);
            a1 = fmaf(q1[c].x, kv.x, a1); a1 = fmaf(q1[c].y, kv.y, a1);
            a1 = fmaf(q1[c].z, kv.z, a1); a1 = fmaf(q1[c].w, kv.w, a1);
        }
        d0[jj] = a0; d1[jj] = a1;
    }
    // Combine halves: lanes l and l^16 hold the two partials of the same pair.
    #pragma unroll
    for (int jj = 0; jj < NR; ++jj) {
        d0[jj] += __shfl_xor_sync(0xffffffffu, d0[jj], 16);
        d1[jj] += __shfl_xor_sync(0xffffffffu, d1[jj], 16);
    }

    // ---- Softmax per query (computed redundantly in both halves; cheap) ----
    float w0[NR], w1[NR];
    {   // query r0: valid slots jj in [0, NR-1) with row in [0, S)
        float m = -CUDART_INF_F;
        #pragma unroll
        for (int jj = 0; jj < NR; ++jj) {
            const int r = r0 - W + jj;
            const bool val = (jj < NR - 1) && (r >= 0) && (r < S);
            w0[jj] = val ? d0[jj] * SCALE : -CUDART_INF_F;
            m = fmaxf(m, w0[jj]);
        }
        float sum = 0.0f;
        #pragma unroll
        for (int jj = 0; jj < NR; ++jj) { w0[jj] = __expf(w0[jj] - m); sum += w0[jj]; }
        const float inv = 1.0f / sum;
        #pragma unroll
        for (int jj = 0; jj < NR; ++jj) w0[jj] *= inv;
    }
    {   // query r0+1: valid slots jj in [1, NR) with row in [0, S)
        float m = -CUDART_INF_F;
        #pragma unroll
        for (int jj = 0; jj < NR; ++jj) {
            const int r = r0 - W + jj;
            const bool val = (jj >= 1) && (r >= 0) && (r < S);
            w1[jj] = val ? d1[jj] * SCALE : -CUDART_INF_F;
            m = fmaxf(m, w1[jj]);
        }
        float sum = 0.0f;
        #pragma unroll
        for (int jj = 0; jj < NR; ++jj) { w1[jj] = __expf(w1[jj] - m); sum += w1[jj]; }
        const float inv = 1.0f / sum;
        #pragma unroll
        for (int jj = 0; jj < NR; ++jj) w1[jj] *= inv;
    }

    // ---- Output: each V chunk read once, accumulated into BOTH query rows ----
    float* o0 = out + gbase + (size_t)r0 * DM + cbase * 4;
    float* o1 = o0 + DM;
    #pragma unroll
    for (int c = 0; c < 8; ++c) {
        float4 a0 = make_float4(0.f, 0.f, 0.f, 0.f);
        float4 a1 = make_float4(0.f, 0.f, 0.f, 0.f);
        #pragma unroll
        for (int jj = 0; jj < NR; ++jj) {
            const float4 vv = *reinterpret_cast<const float4*>(vs + swz(rc[jj], cbase + c));
            const float x0 = w0[jj], x1 = w1[jj];
            a0.x = fmaf(x0, vv.x, a0.x); a0.y = fmaf(x0, vv.y, a0.y);
            a0.z = fmaf(x0, vv.z, a0.z); a0.w = fmaf(x0, vv.w, a0.w);
            a1.x = fmaf(x1, vv.x, a1.x); a1.y = fmaf(x1, vv.y, a1.y);
            a1.z = fmaf(x1, vv.z, a1.z); a1.w = fmaf(x1, vv.w, a1.w);
        }
        reinterpret_cast<float4*>(o0)[c] = a0;
        reinterpret_cast<float4*>(o1)[c] = a1;
    }
}

extern "C" void kernel_launch(void* const* d_in, const int* in_sizes, int n_in,
                              void* d_out, int out_size) {
    const float* q = (const float*)d_in[0];
    const float* k = (const float*)d_in[1];
    const float* v = (const float*)d_in[2];
    float* out = (float*)d_out;

    const int B = in_sizes[0] / (S * DM);  // 256

    static bool attr_set = false;  // idempotent host-side attribute; not a stream op
    if (!attr_set) {
        cudaFuncSetAttribute(banded_attn_kernel,
                             cudaFuncAttributeMaxDynamicSharedMemorySize, SMEM_BYTES);
        attr_set = true;
    }

    dim3 grid(H, B);
    banded_attn_kernel<<<grid, THREADS, SMEM_BYTES>>>(q, k, v, out);
}

// round 6
// speedup vs baseline: 1.4453x; 1.1364x over previous
#include <cuda_runtime.h>
#include <cuda_bf16.h>
#include <math_constants.h>

// Banded sparse attention: B=256, S=128, DM=1024, H=16, Dh=64, half-width W=4.
// One block per (b,h), 128 threads.
// Work unit: 4-lane group {l, l^8, l^16, l^24} owns 4 adjacent queries; each
// lane owns a quarter of the head dim (chunks 4c+quarter, c=0..3 -> the group
// covers contiguous 64B per instruction). Band union of 4 queries = 12 rows,
// so each K/V smem chunk is read once and serves 4 queries (3 row-reads/query).
// Scores are reduced across the 4 lanes with shfl_xor(8) + shfl_xor(16).
// Smem: exact 64-float rows, rotation swizzle (chunk + row>>2) & 15 ->
// conflict-free 8-lane LDS.128 phases under the stride-4 row access pattern.

namespace {
constexpr int S    = 128;
constexpr int DM   = 1024;
constexpr int H    = 16;
constexpr int DH   = 64;
constexpr int W    = 4;
constexpr int QPT  = 4;              // queries per 4-lane group
constexpr int NR   = 2 * W + QPT;    // 12 band-union rows
constexpr float SCALE = 0.125f;

constexpr int THREADS = 128;
constexpr int ROWF = 64;                      // floats per smem row (exact 256B)
constexpr int SMEM_BYTES = 2 * S * ROWF * 4;  // K + V tiles = 65536 B
}  // namespace

__device__ __forceinline__ int swz(int row, int ch) {
    // physical float offset of 16B chunk `ch` of row `row`
    return row * ROWF + (((ch + (row >> 2)) & 15) << 2);
}

__global__ __launch_bounds__(THREADS)
void banded_attn_kernel(const float* __restrict__ q,
                        const float* __restrict__ k,
                        const float* __restrict__ v,
                        float* __restrict__ out) {
    const int h    = blockIdx.x;
    const int b    = blockIdx.y;
    const int tid  = threadIdx.x;
    const int lane = tid & 31;
    const int warp = tid >> 5;

    const int quarter = lane >> 3;          // dim quarter 0..3
    const int g       = lane & 7;           // group index within warp
    const int r0      = (warp * 8 + g) * QPT;  // first query of this group

    extern __shared__ float sm[];
    float* ks = sm;               // [S][ROWF] swizzled
    float* vs = sm + S * ROWF;    // [S][ROWF] swizzled

    const size_t gbase = (size_t)b * S * DM + (size_t)h * DH;

    // ---- This lane's quarter of 4 Q rows (4 chunks each; group covers 64B) ----
    float4 qreg[QPT][4];
    #pragma unroll
    for (int qi = 0; qi < QPT; ++qi) {
        const float* qrow = q + gbase + (size_t)(r0 + qi) * DM;
        #pragma unroll
        for (int c = 0; c < 4; ++c)
            qreg[qi][c] = *reinterpret_cast<const float4*>(qrow + (4 * c + quarter) * 4);
    }

    // ---- Cooperative coalesced K/V staging: 2048 float4/tile, 16 iters ----
    #pragma unroll
    for (int it = 0; it < 16; ++it) {
        const int idx = it * THREADS + tid;
        const int s   = idx >> 4;
        const int d4  = idx & 15;
        const size_t goff = gbase + (size_t)s * DM + d4 * 4;
        const int soff = swz(s, d4);
        *reinterpret_cast<float4*>(ks + soff) = *reinterpret_cast<const float4*>(k + goff);
        *reinterpret_cast<float4*>(vs + soff) = *reinterpret_cast<const float4*>(v + goff);
    }
    __syncthreads();

    // ---- Clamped band-union rows (clamped slots carry weight 0) ----
    int rc[NR];
    #pragma unroll
    for (int jj = 0; jj < NR; ++jj) rc[jj] = min(max(r0 - W + jj, 0), S - 1);

    // ---- Partial scores: each of 12 rows' quarter read ONCE, serves 4 queries ----
    float d[QPT][NR];   // only jj in [qi, qi+2W] is live (compile-time pruned)
    #pragma unroll
    for (int jj = 0; jj < NR; ++jj) {
        float4 kc[4];
        #pragma unroll
        for (int c = 0; c < 4; ++c)
            kc[c] = *reinterpret_cast<const float4*>(ks + swz(rc[jj], 4 * c + quarter));
        #pragma unroll
        for (int qi = 0; qi < QPT; ++qi) {
            if (jj >= qi && jj <= qi + 2 * W) {
                float a = 0.0f;
                #pragma unroll
                for (int c = 0; c < 4; ++c) {
                    a = fmaf(qreg[qi][c].x, kc[c].x, a);
                    a = fmaf(qreg[qi][c].y, kc[c].y, a);
                    a = fmaf(qreg[qi][c].z, kc[c].z, a);
                    a = fmaf(qreg[qi][c].w, kc[c].w, a);
                }
                d[qi][jj] = a;
            }
        }
    }

    // ---- Reduce quarters: lanes {l, l^8, l^16, l^24} hold the 4 partials ----
    #pragma unroll
    for (int qi = 0; qi < QPT; ++qi) {
        #pragma unroll
        for (int jj = qi; jj <= qi + 2 * W; ++jj) {
            d[qi][jj] += __shfl_xor_sync(0xffffffffu, d[qi][jj], 8);
            d[qi][jj] += __shfl_xor_sync(0xffffffffu, d[qi][jj], 16);
        }
    }

    // ---- Softmax per query (redundant across the 4 lanes; 9 slots each) ----
    float wgt[QPT][NR];
    #pragma unroll
    for (int qi = 0; qi < QPT; ++qi) {
        float m = -CUDART_INF_F;
        #pragma unroll
        for (int jj = qi; jj <= qi + 2 * W; ++jj) {
            const int r = r0 - W + jj;
            const bool val = (r >= 0) && (r < S);
            d[qi][jj] = val ? d[qi][jj] * SCALE : -CUDART_INF_F;
            m = fmaxf(m, d[qi][jj]);
        }
        float sum = 0.0f;
        #pragma unroll
        for (int jj = qi; jj <= qi + 2 * W; ++jj) {
            wgt[qi][jj] = __expf(d[qi][jj] - m);   // exp(-inf) = 0 at boundaries
            sum += wgt[qi][jj];
        }
        const float inv = 1.0f / sum;
        #pragma unroll
        for (int jj = qi; jj <= qi + 2 * W; ++jj) wgt[qi][jj] *= inv;
    }

    // ---- Output: each V chunk read once, accumulated into 4 query rows ----
    #pragma unroll
    for (int c = 0; c < 4; ++c) {
        float4 acc[QPT];
        #pragma unroll
        for (int qi = 0; qi < QPT; ++qi) acc[qi] = make_float4(0.f, 0.f, 0.f, 0.f);
        #pragma unroll
        for (int jj = 0; jj < NR; ++jj) {
            const float4 vv = *reinterpret_cast<const float4*>(vs + swz(rc[jj], 4 * c + quarter));
            #pragma unroll
            for (int qi = 0; qi < QPT; ++qi) {
                if (jj >= qi && jj <= qi + 2 * W) {
                    const float x = wgt[qi][jj];
                    acc[qi].x = fmaf(x, vv.x, acc[qi].x);
                    acc[qi].y = fmaf(x, vv.y, acc[qi].y);
                    acc[qi].z = fmaf(x, vv.z, acc[qi].z);
                    acc[qi].w = fmaf(x, vv.w, acc[qi].w);
                }
            }
        }
        #pragma unroll
        for (int qi = 0; qi < QPT; ++qi)
            *reinterpret_cast<float4*>(out + gbase + (size_t)(r0 + qi) * DM
                                       + (4 * c + quarter) * 4) = acc[qi];
    }
}

extern "C" void kernel_launch(void* const* d_in, const int* in_sizes, int n_in,
                              void* d_out, int out_size) {
    const float* q = (const float*)d_in[0];
    const float* k = (const float*)d_in[1];
    const float* v = (const float*)d_in[2];
    float* out = (float*)d_out;

    const int B = in_sizes[0] / (S * DM);  // 256

    static bool attr_set = false;  // idempotent host-side attribute; not a stream op
    if (!attr_set) {
        cudaFuncSetAttribute(banded_attn_kernel,
                             cudaFuncAttributeMaxDynamicSharedMemorySize, SMEM_BYTES);
        attr_set = true;
    }

    dim3 grid(H, B);
    banded_attn_kernel<<<grid, THREADS, SMEM_BYTES>>>(q, k, v, out);
}

// round 8
// speedup vs baseline: 1.9137x; 1.3241x over previous
#include <cuda_runtime.h>
#include <cuda_bf16.h>
#include <math_constants.h>

// Banded sparse attention: B=256, S=128, DM=1024, H=16, Dh=64, half-width W=4.
// One block per (b,h), 128 threads, NO shared memory.
// Work unit: 8-lane group owns 8 adjacent queries; lane `ds` owns dim chunks
// {ds, ds+8} (16B each). Every K/V/Q/out access instruction covers contiguous
// 128B per group -> 4 L1 wavefronts per warp instruction, served from L1 cache
// (within-block row reuse keeps misses at compulsory traffic only).
// Scores: per-(query,row) partials reduced over the 8 dim-slices with
// shfl_xor(1,2,4); softmax held only by the owner lane (lane ds owns query
// r0+ds); weights re-broadcast with shfl in the V accumulation.

namespace {
constexpr int S   = 128;
constexpr int DM  = 1024;
constexpr int H   = 16;
constexpr int W   = 4;
constexpr int QPT = 8;              // queries per 8-lane group
constexpr int NR  = 2 * W + QPT;    // 16 band-union rows per group
constexpr float SCALE = 0.125f;
constexpr int THREADS = 128;        // 4 warps = 16 groups = 128 queries
}  // namespace

__global__ __launch_bounds__(THREADS)
void banded_attn_kernel(const float* __restrict__ q,
                        const float* __restrict__ k,
                        const float* __restrict__ v,
                        float* __restrict__ out) {
    const int h    = blockIdx.x;
    const int b    = blockIdx.y;
    const int tid  = threadIdx.x;
    const int lane = tid & 31;
    const int warp = tid >> 5;

    const int ds  = lane & 7;                  // dim slice 0..7
    const int grp = warp * 4 + (lane >> 3);    // group 0..15
    const int r0  = grp * QPT;                 // first query of this group

    const size_t gbase = (size_t)b * S * DM + (size_t)h * 64;

    // Clamped band-union rows (clamped slots get weight 0 via masking)
    int rc[NR];
    #pragma unroll
    for (int jj = 0; jj < NR; ++jj) rc[jj] = min(max(r0 - W + jj, 0), S - 1);

    // ---- Scores ----
    // s[jj] ends up holding (on lane ds) the full score of query r0+ds vs row
    // r0-W+jj, for jj in [ds, ds+2W]; other slots are masked below.
    float s[NR];
    #pragma unroll
    for (int jj = 0; jj < NR; ++jj) s[jj] = 0.0f;

    {
        // This lane's slices of the 8 Q rows: chunks ds (floats 4ds..) and 8+ds.
        float4 qr[QPT][2];
        #pragma unroll
        for (int qi = 0; qi < QPT; ++qi) {
            const float* qrow = q + gbase + (size_t)(r0 + qi) * DM;
            qr[qi][0] = *reinterpret_cast<const float4*>(qrow + ds * 4);
            qr[qi][1] = *reinterpret_cast<const float4*>(qrow + 32 + ds * 4);
        }

        #pragma unroll
        for (int jj = 0; jj < NR; ++jj) {
            const float* krow = k + gbase + (size_t)rc[jj] * DM;
            const float4 k0 = *reinterpret_cast<const float4*>(krow + ds * 4);
            const float4 k1 = *reinterpret_cast<const float4*>(krow + 32 + ds * 4);
            #pragma unroll
            for (int qi = 0; qi < QPT; ++qi) {
                if (jj >= qi && jj <= qi + 2 * W) {          // live (qi,jj) only
                    float p = 0.0f;
                    p = fmaf(qr[qi][0].x, k0.x, p); p = fmaf(qr[qi][0].y, k0.y, p);
                    p = fmaf(qr[qi][0].z, k0.z, p); p = fmaf(qr[qi][0].w, k0.w, p);
                    p = fmaf(qr[qi][1].x, k1.x, p); p = fmaf(qr[qi][1].y, k1.y, p);
                    p = fmaf(qr[qi][1].z, k1.z, p); p = fmaf(qr[qi][1].w, k1.w, p);
                    // reduce over the 8 dim-slices of this group
                    p += __shfl_xor_sync(0xffffffffu, p, 1);
                    p += __shfl_xor_sync(0xffffffffu, p, 2);
                    p += __shfl_xor_sync(0xffffffffu, p, 4);
                    if (ds == qi) s[jj] = p;                 // owner lane keeps it
                }
            }
        }
    }

    // ---- Softmax (owner lane, query r0+ds, live jj in [ds, ds+2W]) ----
    {
        float m = -CUDART_INF_F;
        #pragma unroll
        for (int jj = 0; jj < NR; ++jj) {
            const int r = r0 - W + jj;
            const bool live = (jj >= ds) && (jj <= ds + 2 * W) && (r >= 0) && (r < S);
            s[jj] = live ? s[jj] * SCALE : -CUDART_INF_F;
            m = fmaxf(m, s[jj]);
        }
        float sum = 0.0f;
        #pragma unroll
        for (int jj = 0; jj < NR; ++jj) { s[jj] = __expf(s[jj] - m); sum += s[jj]; }
        const float inv = 1.0f / sum;
        #pragma unroll
        for (int jj = 0; jj < NR; ++jj) s[jj] *= inv;        // masked slots -> 0
    }

    // ---- Output: each V chunk read once, serves all 8 queries of the group ----
    float4 acc[QPT][2];
    #pragma unroll
    for (int qi = 0; qi < QPT; ++qi) {
        acc[qi][0] = make_float4(0.f, 0.f, 0.f, 0.f);
        acc[qi][1] = make_float4(0.f, 0.f, 0.f, 0.f);
    }

    const int gb = lane & 24;   // group's base lane within the warp
    #pragma unroll
    for (int jj = 0; jj < NR; ++jj) {
        const float* vrow = v + gbase + (size_t)rc[jj] * DM;
        const float4 v0 = *reinterpret_cast<const float4*>(vrow + ds * 4);
        const float4 v1 = *reinterpret_cast<const float4*>(vrow + 32 + ds * 4);
        #pragma unroll
        for (int qi = 0; qi < QPT; ++qi) {
            if (jj >= qi && jj <= qi + 2 * W) {
                // weight for (query r0+qi, row jj) lives in lane gb|qi, reg s[jj]
                const float x = __shfl_sync(0xffffffffu, s[jj], gb | qi);
                acc[qi][0].x = fmaf(x, v0.x, acc[qi][0].x);
                acc[qi][0].y = fmaf(x, v0.y, acc[qi][0].y);
                acc[qi][0].z = fmaf(x, v0.z, acc[qi][0].z);
                acc[qi][0].w = fmaf(x, v0.w, acc[qi][0].w);
                acc[qi][1].x = fmaf(x, v1.x, acc[qi][1].x);
                acc[qi][1].y = fmaf(x, v1.y, acc[qi][1].y);
                acc[qi][1].z = fmaf(x, v1.z, acc[qi][1].z);
                acc[qi][1].w = fmaf(x, v1.w, acc[qi][1].w);
            }
        }
    }

    #pragma unroll
    for (int qi = 0; qi < QPT; ++qi) {
        float* orow = out + gbase + (size_t)(r0 + qi) * DM;
        *reinterpret_cast<float4*>(orow + ds * 4)      = acc[qi][0];
        *reinterpret_cast<float4*>(orow + 32 + ds * 4) = acc[qi][1];
    }
}

extern "C" void kernel_launch(void* const* d_in, const int* in_sizes, int n_in,
                              void* d_out, int out_size) {
    const float* q = (const float*)d_in[0];
    const float* k = (const float*)d_in[1];
    const float* v = (const float*)d_in[2];
    float* out = (float*)d_out;

    const int B = in_sizes[0] / (S * DM);  // 256

    dim3 grid(H, B);
    banded_attn_kernel<<<grid, THREADS>>>(q, k, v, out);
}

// round 9
// speedup vs baseline: 2.1499x; 1.1234x over previous
#include <cuda_runtime.h>
#include <cuda_bf16.h>
#include <math_constants.h>

// Banded sparse attention: B=256, S=128, DM=1024, H=16, Dh=64, half-width W=4.
// Grid (H, 2, B): each block owns 64 consecutive queries of one (b,h) tile.
// 128 threads, NO shared memory. 8-lane group owns 4 adjacent queries; lane
// `ds` owns dim chunks {ds, ds+8} (16B each) -> every K/V/Q/out instruction
// covers contiguous 128B per group (4 L1 wavefronts/warp-instruction).
// QPT=4 keeps per-thread state small (qr/acc 32 regs each) so 5 blocks/SM
// (20 warps) fit -> enough outstanding DRAM loads to push HBM toward peak.

namespace {
constexpr int S   = 128;
constexpr int DM  = 1024;
constexpr int H   = 16;
constexpr int W   = 4;
constexpr int QPT = 4;              // queries per 8-lane group
constexpr int NR  = 2 * W + QPT;    // 12 band-union rows per group
constexpr float SCALE = 0.125f;
constexpr int THREADS = 128;        // 4 warps = 16 groups = 64 queries/block
}  // namespace

__global__ __launch_bounds__(THREADS, 5)
void banded_attn_kernel(const float* __restrict__ q,
                        const float* __restrict__ k,
                        const float* __restrict__ v,
                        float* __restrict__ out) {
    const int h    = blockIdx.x;
    const int half = blockIdx.y;     // which 64-query half of the tile
    const int b    = blockIdx.z;
    const int tid  = threadIdx.x;
    const int lane = tid & 31;
    const int warp = tid >> 5;

    const int ds  = lane & 7;                          // dim slice 0..7
    const int grp = warp * 4 + (lane >> 3);            // group 0..15
    const int r0  = half * 64 + grp * QPT;             // first query of group

    const size_t gbase = (size_t)b * S * DM + (size_t)h * 64;

    // Clamped band-union rows (clamped slots masked to weight 0 later)
    int rc[NR];
    #pragma unroll
    for (int jj = 0; jj < NR; ++jj) rc[jj] = min(max(r0 - W + jj, 0), S - 1);

    // ---- Scores ----
    // On owner lane ds==qi (qi<4): s[jj] = score of query r0+qi vs row r0-W+jj.
    float s[NR];
    #pragma unroll
    for (int jj = 0; jj < NR; ++jj) s[jj] = 0.0f;

    {
        // This lane's slices of the 4 Q rows (chunks ds and ds+8)
        float4 qr[QPT][2];
        #pragma unroll
        for (int qi = 0; qi < QPT; ++qi) {
            const float* qrow = q + gbase + (size_t)(r0 + qi) * DM;
            qr[qi][0] = *reinterpret_cast<const float4*>(qrow + ds * 4);
            qr[qi][1] = *reinterpret_cast<const float4*>(qrow + 32 + ds * 4);
        }

        #pragma unroll
        for (int jj = 0; jj < NR; ++jj) {
            const float* krow = k + gbase + (size_t)rc[jj] * DM;
            const float4 k0 = *reinterpret_cast<const float4*>(krow + ds * 4);
            const float4 k1 = *reinterpret_cast<const float4*>(krow + 32 + ds * 4);
            #pragma unroll
            for (int qi = 0; qi < QPT; ++qi) {
                if (jj >= qi && jj <= qi + 2 * W) {       // live (qi,jj) only
                    float p = 0.0f;
                    p = fmaf(qr[qi][0].x, k0.x, p); p = fmaf(qr[qi][0].y, k0.y, p);
                    p = fmaf(qr[qi][0].z, k0.z, p); p = fmaf(qr[qi][0].w, k0.w, p);
                    p = fmaf(qr[qi][1].x, k1.x, p); p = fmaf(qr[qi][1].y, k1.y, p);
                    p = fmaf(qr[qi][1].z, k1.z, p); p = fmaf(qr[qi][1].w, k1.w, p);
                    // reduce over the 8 dim-slices of this group
                    p += __shfl_xor_sync(0xffffffffu, p, 1);
                    p += __shfl_xor_sync(0xffffffffu, p, 2);
                    p += __shfl_xor_sync(0xffffffffu, p, 4);
                    if (ds == qi) s[jj] = p;              // owner lane keeps it
                }
            }
        }
    }

    // ---- Softmax (owner lanes ds<4; query r0+ds, live jj in [ds, ds+2W]) ----
    {
        float m = -CUDART_INF_F;
        #pragma unroll
        for (int jj = 0; jj < NR; ++jj) {
            const int r = r0 - W + jj;
            const bool live = (jj >= ds) && (jj <= ds + 2 * W) && (r >= 0) && (r < S);
            s[jj] = live ? s[jj] * SCALE : -CUDART_INF_F;
            m = fmaxf(m, s[jj]);
        }
        float sum = 0.0f;
        #pragma unroll
        for (int jj = 0; jj < NR; ++jj) { s[jj] = __expf(s[jj] - m); sum += s[jj]; }
        const float inv = 1.0f / sum;
        #pragma unroll
        for (int jj = 0; jj < NR; ++jj) s[jj] *= inv;     // masked slots -> 0
    }

    // ---- Output: each V chunk read once, serves all 4 queries of the group ----
    float4 acc[QPT][2];
    #pragma unroll
    for (int qi = 0; qi < QPT; ++qi) {
        acc[qi][0] = make_float4(0.f, 0.f, 0.f, 0.f);
        acc[qi][1] = make_float4(0.f, 0.f, 0.f, 0.f);
    }

    const int gb = lane & 24;   // group's base lane within the warp
    #pragma unroll
    for (int jj = 0; jj < NR; ++jj) {
        const float* vrow = v + gbase + (size_t)rc[jj] * DM;
        const float4 v0 = *reinterpret_cast<const float4*>(vrow + ds * 4);
        const float4 v1 = *reinterpret_cast<const float4*>(vrow + 32 + ds * 4);
        #pragma unroll
        for (int qi = 0; qi < QPT; ++qi) {
            if (jj >= qi && jj <= qi + 2 * W) {
                // weight for (query r0+qi, row jj) lives in lane gb|qi, reg s[jj]
                const float x = __shfl_sync(0xffffffffu, s[jj], gb | qi);
                acc[qi][0].x = fmaf(x, v0.x, acc[qi][0].x);
                acc[qi][0].y = fmaf(x, v0.y, acc[qi][0].y);
                acc[qi][0].z = fmaf(x, v0.z, acc[qi][0].z);
                acc[qi][0].w = fmaf(x, v0.w, acc[qi][0].w);
                acc[qi][1].x = fmaf(x, v1.x, acc[qi][1].x);
                acc[qi][1].y = fmaf(x, v1.y, acc[qi][1].y);
                acc[qi][1].z = fmaf(x, v1.z, acc[qi][1].z);
                acc[qi][1].w = fmaf(x, v1.w, acc[qi][1].w);
            }
        }
    }

    #pragma unroll
    for (int qi = 0; qi < QPT; ++qi) {
        float* orow = out + gbase + (size_t)(r0 + qi) * DM;
        *reinterpret_cast<float4*>(orow + ds * 4)      = acc[qi][0];
        *reinterpret_cast<float4*>(orow + 32 + ds * 4) = acc[qi][1];
    }
}

extern "C" void kernel_launch(void* const* d_in, const int* in_sizes, int n_in,
                              void* d_out, int out_size) {
    const float* q = (const float*)d_in[0];
    const float* k = (const float*)d_in[1];
    const float* v = (const float*)d_in[2];
    float* out = (float*)d_out;

    const int B = in_sizes[0] / (S * DM);  // 256

    dim3 grid(H, 2, B);
    banded_attn_kernel<<<grid, THREADS>>>(q, k, v, out);
}